// round 15
// baseline (speedup 1.0000x reference)
#include <cuda_runtime.h>
#include <cuda_fp16.h>

#define N   128
#define N2  (128 * 128)
#define N3  (128 * 128 * 128)

// Scratch (no allocations allowed)
__device__ float  g_warped[N3];         // fp32: feeds gradients/denominator
__device__ __half g_vfh[3 * N3];        // fp16 internal velocity field
__device__ __half g_uh[3 * N3];         // fp16 u = vf + f (W-smoothed)
__device__ __half g_th[3 * N3];         // fp16 D-smoothed intermediate
__device__ __half g_fgh[3 * N3];        // fp16 fixed-image gradient (precomputed once)

// Gaussian weights sigma=1, radius=3, normalized
__constant__ float GW[4] = {0.39905027f, 0.24203622f, 0.05400558f, 0.00443305f};

// ---- fp16 pack/unpack helpers ----
__device__ __forceinline__ float2 h2_to_f2(unsigned x) {
    __half2 h = *reinterpret_cast<__half2*>(&x);
    return __half22float2(h);
}
__device__ __forceinline__ unsigned f2_to_h2(float a, float b) {
    __half2 h = __floats2half2_rn(a, b);
    return *reinterpret_cast<unsigned*>(&h);
}
__device__ __forceinline__ float4 ld_h4(const uint2* __restrict__ p, int idx) {
    uint2 v = p[idx];
    float2 fa = h2_to_f2(v.x), fb = h2_to_f2(v.y);
    return make_float4(fa.x, fa.y, fb.x, fb.y);
}
__device__ __forceinline__ void st_h4(uint2* __restrict__ p, int idx, float4 v) {
    uint2 u;
    u.x = f2_to_h2(v.x, v.y);
    u.y = f2_to_h2(v.z, v.w);
    p[idx] = u;
}
__device__ __forceinline__ void ld_h8(const uint4* __restrict__ p, int idx, float* f) {
    uint4 v = p[idx];
    float2 a = h2_to_f2(v.x), b = h2_to_f2(v.y), c = h2_to_f2(v.z), d = h2_to_f2(v.w);
    f[0] = a.x; f[1] = a.y; f[2] = b.x; f[3] = b.y;
    f[4] = c.x; f[5] = c.y; f[6] = d.x; f[7] = d.y;
}
__device__ __forceinline__ void st_h8(uint4* __restrict__ p, int idx, const float* f) {
    uint4 v;
    v.x = f2_to_h2(f[0], f[1]);
    v.y = f2_to_h2(f[2], f[3]);
    v.z = f2_to_h2(f[4], f[5]);
    v.w = f2_to_h2(f[6], f[7]);
    p[idx] = v;
}

__global__ void zero_h_kernel(uint4* __restrict__ vfh) {
    int i = blockIdx.x * blockDim.x + threadIdx.x;
    if (i < 3 * N3 / 8) vfh[i] = make_uint4(0u, 0u, 0u, 0u);
}

// ---------------------------------------------------------------------------
// Shared gradient helpers (jnp.gradient: one-sided at edges, central inside)
// ---------------------------------------------------------------------------
__device__ __forceinline__ float4 grad_s(const float4* __restrict__ a4,
                                         int i4, int c, int s4) {
    float4 p, m;
    if (c == 0) {
        p = a4[i4 + s4]; m = a4[i4];
        return make_float4(p.x - m.x, p.y - m.y, p.z - m.z, p.w - m.w);
    }
    if (c == 127) {
        p = a4[i4]; m = a4[i4 - s4];
        return make_float4(p.x - m.x, p.y - m.y, p.z - m.z, p.w - m.w);
    }
    p = a4[i4 + s4]; m = a4[i4 - s4];
    return make_float4(0.5f * (p.x - m.x), 0.5f * (p.y - m.y),
                       0.5f * (p.z - m.z), 0.5f * (p.w - m.w));
}

__device__ __forceinline__ float4 grad_w_shfl(float4 c, int lane) {
    float lw = __shfl_up_sync(0xFFFFFFFFu, c.w, 1);    // value at w0-1
    float rx = __shfl_down_sync(0xFFFFFFFFu, c.x, 1);  // value at w0+4
    float4 g;
    g.x = (lane == 0)  ? (c.y - c.x) : 0.5f * (c.y - lw);
    g.y = 0.5f * (c.z - c.x);
    g.z = 0.5f * (c.w - c.y);
    g.w = (lane == 31) ? (c.w - c.z) : 0.5f * (rx - c.z);
    return g;
}

// ---------------------------------------------------------------------------
// One-time: fixed-image spatial gradient -> fp16 (3 channels)
// ---------------------------------------------------------------------------
__global__ void fixed_grad_kernel(const float4* __restrict__ fixed4,
                                  uint2* __restrict__ fgh) {
    int i4 = blockIdx.x * blockDim.x + threadIdx.x;   // over N3/4
    if (i4 >= N3 / 4) return;
    int i = i4 * 4;
    int h = (i >> 7) & 127;
    int d = i >> 14;
    int lane = threadIdx.x & 31;

    float4 fc = fixed4[i4];
    st_h4(fgh, i4,              grad_s(fixed4, i4, d, N2 / 4));
    st_h4(fgh, i4 + N3 / 4,     grad_s(fixed4, i4, h, N / 4));
    st_h4(fgh, i4 + 2 * N3 / 4, grad_w_shfl(fc, lane));
}

// ---------------------------------------------------------------------------
// Trilinear warp (4 consecutive-w voxels per thread); vf read as fp16.
// map_coordinates(order=1, mode='nearest') == clamp coordinate to [0, N-1].
// ---------------------------------------------------------------------------
__device__ __forceinline__ float trilerp(const float* __restrict__ m,
                                         float cd, float ch, float cw) {
    cd = fminf(fmaxf(cd, 0.0f), 127.0f);
    ch = fminf(fmaxf(ch, 0.0f), 127.0f);
    cw = fminf(fmaxf(cw, 0.0f), 127.0f);
    int d0 = (int)cd, h0 = (int)ch, w0 = (int)cw;
    float fd = cd - (float)d0, fh = ch - (float)h0, fw = cw - (float)w0;
    int d1 = min(d0 + 1, 127), h1 = min(h0 + 1, 127), w1 = min(w0 + 1, 127);

    const float* p0 = m + (d0 << 14);
    const float* p1 = m + (d1 << 14);
    int r0 = (h0 << 7), r1 = (h1 << 7);

    float v000 = p0[r0 + w0], v001 = p0[r0 + w1];
    float v010 = p0[r1 + w0], v011 = p0[r1 + w1];
    float v100 = p1[r0 + w0], v101 = p1[r0 + w1];
    float v110 = p1[r1 + w0], v111 = p1[r1 + w1];

    float c00 = v000 + fw * (v001 - v000);
    float c01 = v010 + fw * (v011 - v010);
    float c10 = v100 + fw * (v101 - v100);
    float c11 = v110 + fw * (v111 - v110);
    float c0 = c00 + fh * (c01 - c00);
    float c1 = c10 + fh * (c11 - c10);
    return c0 + fd * (c1 - c0);
}

__global__ void warp_kernel(const float* __restrict__ moving,
                            const uint2* __restrict__ vfh,
                            float4* __restrict__ warped4) {
    int i4 = blockIdx.x * blockDim.x + threadIdx.x;   // over N3/4
    if (i4 >= N3 / 4) return;
    int i = i4 * 4;
    int w = i & 127;
    int h = (i >> 7) & 127;
    int d = i >> 14;

    float4 vd = ld_h4(vfh, i4);
    float4 vh = ld_h4(vfh, i4 + N3 / 4);
    float4 vw = ld_h4(vfh, i4 + 2 * N3 / 4);

    float4 out;
    out.x = trilerp(moving, (float)d + vd.x, (float)h + vh.x, (float)(w + 0) + vw.x);
    out.y = trilerp(moving, (float)d + vd.y, (float)h + vh.y, (float)(w + 1) + vw.y);
    out.z = trilerp(moving, (float)d + vd.z, (float)h + vh.z, (float)(w + 2) + vw.z);
    out.w = trilerp(moving, (float)d + vd.w, (float)h + vh.w, (float)(w + 3) + vw.w);
    warped4[i4] = out;
}

// ---------------------------------------------------------------------------
// Demon forces (dual, using precomputed fixed gradient) + u = vf + f,
// then W-axis 7-tap smooth via warp shuffle.
// ---------------------------------------------------------------------------
__device__ __forceinline__ float4 wsmooth_shfl(float4 u, int lane) {
    float ly = __shfl_up_sync(0xFFFFFFFFu, u.y, 1);
    float lz = __shfl_up_sync(0xFFFFFFFFu, u.z, 1);
    float lw = __shfl_up_sync(0xFFFFFFFFu, u.w, 1);
    float rx = __shfl_down_sync(0xFFFFFFFFu, u.x, 1);
    float ry = __shfl_down_sync(0xFFFFFFFFu, u.y, 1);
    float rz = __shfl_down_sync(0xFFFFFFFFu, u.z, 1);
    if (lane == 0)  { ly = 0.f; lz = 0.f; lw = 0.f; }
    if (lane == 31) { rx = 0.f; ry = 0.f; rz = 0.f; }
    float a[10] = {ly, lz, lw, u.x, u.y, u.z, u.w, rx, ry, rz};
    float4 o;
#pragma unroll
    for (int j = 0; j < 4; j++) {
        float acc = GW[0] * a[3 + j];
#pragma unroll
        for (int t = 1; t <= 3; t++)
            acc += GW[t] * (a[3 + j - t] + a[3 + j + t]);
        ((float*)&o)[j] = acc;
    }
    return o;
}

__global__ void force_w_kernel(const float4* __restrict__ warped4,
                               const float4* __restrict__ fixed4,
                               const uint2* __restrict__ fgh,
                               const uint2* __restrict__ vfh,
                               uint2* __restrict__ uh) {
    int i4 = blockIdx.x * blockDim.x + threadIdx.x;   // over N3/4
    if (i4 >= N3 / 4) return;
    int i = i4 * 4;
    int h = (i >> 7) & 127;
    int d = i >> 14;
    int lane = threadIdx.x & 31;   // == w4 index within the row

    float4 wc = warped4[i4];
    float4 fc = fixed4[i4];

    float4 gdw = grad_s(warped4, i4, d, N2 / 4);
    float4 ghw = grad_s(warped4, i4, h, N / 4);
    float4 gww = grad_w_shfl(wc, lane);

    float4 gdf = ld_h4(fgh, i4);
    float4 ghf = ld_h4(fgh, i4 + N3 / 4);
    float4 gwf = ld_h4(fgh, i4 + 2 * N3 / 4);

    float4 v0 = ld_h4(vfh, i4);
    float4 v1 = ld_h4(vfh, i4 + N3 / 4);
    float4 v2 = ld_h4(vfh, i4 + 2 * N3 / 4);

    float4 u0, u1, u2;
#pragma unroll
    for (int j = 0; j < 4; j++) {
        float diff = ((const float*)&wc)[j] - ((const float*)&fc)[j];
        float g0 = 0.5f * (((const float*)&gdw)[j] + ((const float*)&gdf)[j]);
        float g1 = 0.5f * (((const float*)&ghw)[j] + ((const float*)&ghf)[j]);
        float g2 = 0.5f * (((const float*)&gww)[j] + ((const float*)&gwf)[j]);
        float denom = g0 * g0 + g1 * g1 + g2 * g2 + diff * diff;
        float s = (denom > 1e-6f) ? (diff / denom) : 0.0f;
        ((float*)&u0)[j] = ((const float*)&v0)[j] + s * g0;
        ((float*)&u1)[j] = ((const float*)&v1)[j] + s * g1;
        ((float*)&u2)[j] = ((const float*)&v2)[j] + s * g2;
    }

    // Fused W-axis smoothing (separable passes commute)
    st_h4(uh, i4,              wsmooth_shfl(u0, lane));
    st_h4(uh, i4 + N3 / 4,     wsmooth_shfl(u1, lane));
    st_h4(uh, i4 + 2 * N3 / 4, wsmooth_shfl(u2, lane));
}

// ---------------------------------------------------------------------------
// Strided-axis 7-tap Gaussian: 4 outputs along the axis x 8 voxels wide (uint4),
// fp16 I/O, fp32 accumulate. Accumulate-on-load keeps registers modest.
// Layout (uint4 granularity = 8 voxels): [outer][axis=128][INNER8].
// D axis: INNER8 = N2/8. H axis: INNER8 = N/8.
// 32-bit indexing throughout (max index 3*N3/8 < 2^31).
// ---------------------------------------------------------------------------
template <int INNER8>
__global__ void smooth_s8_h_kernel(const uint4* __restrict__ in,
                                   uint4* __restrict__ out) {
    int t = blockIdx.x * blockDim.x + threadIdx.x;    // over 3*N3/32
    if (t >= 3 * N3 / 32) return;
    int inner = t % INNER8;
    int cb    = (t / INNER8) & 31;
    int outer = t / (INNER8 * 32);
    int c0 = cb * 4;
    int base = outer * (128 * INNER8) + inner;

    const uint4* p = in + base;

    float acc[4][8];
#pragma unroll
    for (int k = 0; k < 4; k++)
#pragma unroll
        for (int m = 0; m < 8; m++) acc[k][m] = 0.f;

#pragma unroll
    for (int j = 0; j < 10; j++) {
        int c = c0 + j - 3;
        if (c < 0 || c > 127) continue;   // zero padding
        float f[8];
        ld_h8(p, c * INNER8, f);
#pragma unroll
        for (int k = 0; k < 4; k++) {
            int dist = j - 3 - k; dist = dist < 0 ? -dist : dist;
            if (dist <= 3) {
                float w = GW[dist];
#pragma unroll
                for (int m = 0; m < 8; m++) acc[k][m] += w * f[m];
            }
        }
    }

    uint4* q = out + base;
#pragma unroll
    for (int k = 0; k < 4; k++)
        st_h8(q, (c0 + k) * INNER8, acc[k]);
}

// H-axis variant writing fp32 to d_out (final iteration). INNER8 = N/8.
__global__ void smooth_s8_out_kernel(const uint4* __restrict__ in,
                                     float4* __restrict__ out4) {
    const int INNER8 = N / 8;
    int t = blockIdx.x * blockDim.x + threadIdx.x;    // over 3*N3/32
    if (t >= 3 * N3 / 32) return;
    int inner = t % INNER8;
    int cb    = (t / INNER8) & 31;
    int outer = t / (INNER8 * 32);   // (ch, d): 3*128 outers
    int c0 = cb * 4;

    const uint4* p = in + outer * (128 * INNER8) + inner;

    float acc[4][8];
#pragma unroll
    for (int k = 0; k < 4; k++)
#pragma unroll
        for (int m = 0; m < 8; m++) acc[k][m] = 0.f;

#pragma unroll
    for (int j = 0; j < 10; j++) {
        int c = c0 + j - 3;
        if (c < 0 || c > 127) continue;
        float f[8];
        ld_h8(p, c * INNER8, f);
#pragma unroll
        for (int k = 0; k < 4; k++) {
            int dist = j - 3 - k; dist = dist < 0 ? -dist : dist;
            if (dist <= 3) {
                float w = GW[dist];
#pragma unroll
                for (int m = 0; m < 8; m++) acc[k][m] += w * f[m];
            }
        }
    }

    // fp32 store: voxel base = outer*N2 + c*N + inner*8
#pragma unroll
    for (int k = 0; k < 4; k++) {
        int f4idx = outer * (N2 / 4) + (c0 + k) * (N / 4) + inner * 2;
        out4[f4idx]     = make_float4(acc[k][0], acc[k][1], acc[k][2], acc[k][3]);
        out4[f4idx + 1] = make_float4(acc[k][4], acc[k][5], acc[k][6], acc[k][7]);
    }
}

extern "C" void kernel_launch(void* const* d_in, const int* in_sizes, int n_in,
                              void* d_out, int out_size) {
    const float* moving = (const float*)d_in[0];
    const float4* fixed4 = (const float4*)d_in[1];
    float4* vf_out = (float4*)d_out;

    float *warped_p; __half *vfh_p, *uh_p, *th_p, *fgh_p;
    cudaGetSymbolAddress((void**)&warped_p, g_warped);
    cudaGetSymbolAddress((void**)&vfh_p, g_vfh);
    cudaGetSymbolAddress((void**)&uh_p, g_uh);
    cudaGetSymbolAddress((void**)&th_p, g_th);
    cudaGetSymbolAddress((void**)&fgh_p, g_fgh);
    float4* warped4 = (float4*)warped_p;
    uint2* vfh = (uint2*)vfh_p;
    uint2* uh  = (uint2*)uh_p;
    uint2* fgh = (uint2*)fgh_p;

    const int T = 256;
    const int B1 = (N3 / 4) / T;            // 2048
    const int BZ8 = (3 * N3 / 8) / T;       // 3072
    const int BS8 = (3 * N3 / 32) / T;      // 768

    zero_h_kernel<<<BZ8, T>>>((uint4*)vfh);
    fixed_grad_kernel<<<B1, T>>>(fixed4, fgh);

    for (int it = 0; it < 20; it++) {
        warp_kernel<<<B1, T>>>(moving, vfh, warped4);
        force_w_kernel<<<B1, T>>>(warped4, fixed4, fgh, vfh, uh);   // force + W smooth
        smooth_s8_h_kernel<N2 / 8><<<BS8, T>>>((const uint4*)uh, (uint4*)th_p);  // D
        if (it < 19)
            smooth_s8_h_kernel<N / 8><<<BS8, T>>>((const uint4*)th_p, (uint4*)vfh); // H
        else
            smooth_s8_out_kernel<<<BS8, T>>>((const uint4*)th_p, vf_out);  // final fp32
    }
}